// round 1
// baseline (speedup 1.0000x reference)
#include <cuda_runtime.h>
#include <cuda_bf16.h>

// Sparsemax along last dim, rows of N=2048 fp32.
// One block (256 threads) per row. Row held in registers (8 vals/thread).
// Water-filling fixed point for tau:
//   tau0 = (sum - 1)/N
//   repeat: support = {x > tau}; tau = (sum(support) - 1)/|support|
// Converges exactly when the support is stable. Survivors are compacted into
// shared memory (ping-pong) each iteration, so per-iteration work shrinks
// geometrically (~2048 -> ~1024 -> ~430 -> ... for Gaussian rows).

constexpr int ROW_N   = 2048;
constexpr int THREADS = 256;
constexpr int VPT     = ROW_N / THREADS;   // 8
constexpr int NWARP   = THREADS / 32;      // 8

__global__ __launch_bounds__(THREADS, 8)
void sparsemax_kernel(const float* __restrict__ in, float* __restrict__ out) {
    __shared__ float listA[ROW_N];
    __shared__ float listB[ROW_N];
    __shared__ float ps[NWARP];
    __shared__ float pc[NWARP];
    __shared__ int   cbuf[2];

    const int t    = threadIdx.x;
    const int lane = t & 31;
    const int warp = t >> 5;
    const size_t row = blockIdx.x;

    const float4* x4 = (const float4*)(in + row * (size_t)ROW_N);
    float4 a0 = x4[t];
    float4 a1 = x4[t + THREADS];
    float v[VPT] = {a0.x, a0.y, a0.z, a0.w, a1.x, a1.y, a1.z, a1.w};

    // ---- initial total sum -> tau0 = (sum - 1)/N ----
    float s = 0.f;
#pragma unroll
    for (int j = 0; j < VPT; j++) s += v[j];
#pragma unroll
    for (int o = 16; o; o >>= 1) s += __shfl_down_sync(0xffffffffu, s, o);
    if (lane == 0) ps[warp] = s;
    if (t == 0) { cbuf[0] = 0; cbuf[1] = 0; }
    __syncthreads();

    float tau;
    {
        float tot = 0.f;
#pragma unroll
        for (int w = 0; w < NWARP; w++) tot += ps[w];
        tau = (tot - 1.0f) * (1.0f / (float)ROW_N);
    }

    // ---- compact {v > tau0} from registers into listA; accumulate (S, C) ----
    float ms = 0.f, mc = 0.f;
    int nloc = 0;
#pragma unroll
    for (int j = 0; j < VPT; j++) {
        if (v[j] > tau) { ms += v[j]; mc += 1.0f; nloc++; }
    }
    int base = atomicAdd(&cbuf[0], nloc);
#pragma unroll
    for (int j = 0; j < VPT; j++) {
        if (v[j] > tau) listA[base++] = v[j];
    }
#pragma unroll
    for (int o = 16; o; o >>= 1) {
        ms += __shfl_down_sync(0xffffffffu, ms, o);
        mc += __shfl_down_sync(0xffffffffu, mc, o);
    }
    if (lane == 0) { ps[warp] = ms; pc[warp] = mc; }
    __syncthreads();

    float S = 0.f, C = 0.f;
#pragma unroll
    for (int w = 0; w < NWARP; w++) { S += ps[w]; C += pc[w]; }
    int cnt = (int)C;

    if (cnt == ROW_N) {
        // entire row is the support: tau = (sum - 1)/N already the fixed point
        tau = (S - 1.0f) * (1.0f / (float)ROW_N);
    } else {
        tau = (S - 1.0f) / C;           // tau computed FROM the set in listA
        float* cur = listA;
        float* nxt = listB;
        int pingpong = 1;               // next compaction counter = cbuf[1]

        // cnt strictly decreases each iteration until stable, so this
        // terminates; 256 is a generous safety cap.
        for (int iter = 0; iter < 256; ++iter) {
            float s2 = 0.f, c2 = 0.f;
            int nl = 0;
            for (int k = t; k < cnt; k += THREADS) {
                float w = cur[k];
                if (w > tau) { s2 += w; c2 += 1.0f; nl++; }
            }
            int b2 = atomicAdd(&cbuf[pingpong], nl);
            for (int k = t; k < cnt; k += THREADS) {
                float w = cur[k];
                if (w > tau) nxt[b2++] = w;
            }
#pragma unroll
            for (int o = 16; o; o >>= 1) {
                s2 += __shfl_down_sync(0xffffffffu, s2, o);
                c2 += __shfl_down_sync(0xffffffffu, c2, o);
            }
            if (lane == 0) { ps[warp] = s2; pc[warp] = c2; }
            // zero the counter for the NEXT iteration (its last use finished
            // before the previous __syncthreads; next use is after this one)
            if (t == 0) cbuf[pingpong ^ 1] = 0;
            __syncthreads();

            float S2 = 0.f, C2 = 0.f;
#pragma unroll
            for (int w2 = 0; w2 < NWARP; w2++) { S2 += ps[w2]; C2 += pc[w2]; }
            int ncnt = (int)C2;
            tau = (S2 - 1.0f) / C2;     // tau from the set now in nxt
            if (ncnt == cnt) break;     // support stable -> exact fixed point
            cnt = ncnt;
            float* tmp = cur; cur = nxt; nxt = tmp;
            pingpong ^= 1;
        }
    }

    // ---- write output: relu(x - tau), from the preserved registers ----
    float4 o0, o1;
    o0.x = fmaxf(v[0] - tau, 0.f);
    o0.y = fmaxf(v[1] - tau, 0.f);
    o0.z = fmaxf(v[2] - tau, 0.f);
    o0.w = fmaxf(v[3] - tau, 0.f);
    o1.x = fmaxf(v[4] - tau, 0.f);
    o1.y = fmaxf(v[5] - tau, 0.f);
    o1.z = fmaxf(v[6] - tau, 0.f);
    o1.w = fmaxf(v[7] - tau, 0.f);

    float4* y4 = (float4*)(out + row * (size_t)ROW_N);
    y4[t]           = o0;
    y4[t + THREADS] = o1;
}

extern "C" void kernel_launch(void* const* d_in, const int* in_sizes, int n_in,
                              void* d_out, int out_size) {
    const float* in = (const float*)d_in[0];
    float* out = (float*)d_out;
    int rows = in_sizes[0] / ROW_N;   // 2*16*2048 = 65536
    sparsemax_kernel<<<rows, THREADS>>>(in, out);
}

// round 2
// speedup vs baseline: 3.5361x; 3.5361x over previous
#include <cuda_runtime.h>
#include <cuda_bf16.h>

// Sparsemax along last dim, rows of N=2048 fp32.
//
// Key bound: sum_i relu(x_i - tau) = 1 and relu(M - tau) <= 1 (M = row max)
// imply tau in [M-1, M). So support(tau) is a subset of {x > M-1}.
// For Gaussian rows this candidate set is ~4-10 elements of 2048.
//
// Per row (one 256-thread block):
//   1. register pass -> M (block max reduce)
//   2. register pass -> compact {x > M-1} to shared + (S, C);
//      Newton start tau1 = (S-1)/C  (>= M-1, <= tau*, monotone from below)
//   3. warp 0 alone runs the Newton fixed point on the tiny list
//      (no block barriers, butterfly shfl reductions)
//   4. broadcast tau, emit relu(x - tau) from registers.
// Degenerate inputs (many candidates, up to all 2048) remain correct via the
// generic warp-0 strided loop; they just run slower.

constexpr int ROW_N   = 2048;
constexpr int THREADS = 256;
constexpr int VPT     = ROW_N / THREADS;   // 8
constexpr int NWARP   = THREADS / 32;      // 8

__global__ __launch_bounds__(THREADS, 8)
void sparsemax_kernel(const float* __restrict__ in, float* __restrict__ out) {
    __shared__ float list[ROW_N];
    __shared__ float pm[NWARP];
    __shared__ float ps[NWARP];
    __shared__ float pc[NWARP];
    __shared__ int   scount;
    __shared__ float stau;

    const int t    = threadIdx.x;
    const int lane = t & 31;
    const int warp = t >> 5;
    const size_t row = blockIdx.x;

    const float4* x4 = (const float4*)(in + row * (size_t)ROW_N);
    float4 a0 = x4[t];
    float4 a1 = x4[t + THREADS];
    float v[VPT] = {a0.x, a0.y, a0.z, a0.w, a1.x, a1.y, a1.z, a1.w};

    // ---- pass 1: row max ----
    float m = v[0];
#pragma unroll
    for (int j = 1; j < VPT; j++) m = fmaxf(m, v[j]);
#pragma unroll
    for (int o = 16; o; o >>= 1) m = fmaxf(m, __shfl_xor_sync(0xffffffffu, m, o));
    if (lane == 0) pm[warp] = m;
    if (t == 0) scount = 0;
    __syncthreads();

    float M = pm[0];
#pragma unroll
    for (int w = 1; w < NWARP; w++) M = fmaxf(M, pm[w]);
    const float thr = M - 1.0f;

    // ---- pass 2: compact candidates {x > M-1}, accumulate (S, C) ----
    float s = 0.f, c = 0.f;
    float loc[VPT];
    int nloc = 0;
#pragma unroll
    for (int j = 0; j < VPT; j++) {
        if (v[j] > thr) { s += v[j]; c += 1.0f; loc[nloc++] = v[j]; }
    }
    if (nloc) {                            // extremely rare per thread
        int base = atomicAdd(&scount, nloc);
        for (int i = 0; i < nloc; i++) list[base + i] = loc[i];
    }
#pragma unroll
    for (int o = 16; o; o >>= 1) {
        s += __shfl_down_sync(0xffffffffu, s, o);
        c += __shfl_down_sync(0xffffffffu, c, o);
    }
    if (lane == 0) { ps[warp] = s; pc[warp] = c; }
    __syncthreads();

    // ---- warp 0: Newton fixed point on the candidate list ----
    if (warp == 0) {
        float S = ps[0], C = pc[0];
#pragma unroll
        for (int w = 1; w < NWARP; w++) { S += ps[w]; C += pc[w]; }
        const int cnt = scount;            // == (int)C
        float tau = (S - 1.0f) / C;        // first Newton step from thr
        int kprev = cnt;

        for (int iter = 0; iter < 64; ++iter) {
            float s2 = 0.f, c2 = 0.f;
            for (int k = lane; k < cnt; k += 32) {
                float w = list[k];
                if (w > tau) { s2 += w; c2 += 1.0f; }
            }
#pragma unroll
            for (int o = 16; o; o >>= 1) {
                s2 += __shfl_xor_sync(0xffffffffu, s2, o);
                c2 += __shfl_xor_sync(0xffffffffu, c2, o);
            }
            int k2 = (int)c2;              // max element always survives -> c2 >= 1
            tau = (s2 - 1.0f) / c2;
            if (k2 == kprev) break;        // support stable -> exact fixed point
            kprev = k2;
        }
        if (lane == 0) stau = tau;
    }
    __syncthreads();

    // ---- output: relu(x - tau) from preserved registers ----
    const float tau = stau;
    float4 o0, o1;
    o0.x = fmaxf(v[0] - tau, 0.f);
    o0.y = fmaxf(v[1] - tau, 0.f);
    o0.z = fmaxf(v[2] - tau, 0.f);
    o0.w = fmaxf(v[3] - tau, 0.f);
    o1.x = fmaxf(v[4] - tau, 0.f);
    o1.y = fmaxf(v[5] - tau, 0.f);
    o1.z = fmaxf(v[6] - tau, 0.f);
    o1.w = fmaxf(v[7] - tau, 0.f);

    float4* y4 = (float4*)(out + row * (size_t)ROW_N);
    y4[t]           = o0;
    y4[t + THREADS] = o1;
}

extern "C" void kernel_launch(void* const* d_in, const int* in_sizes, int n_in,
                              void* d_out, int out_size) {
    const float* in = (const float*)d_in[0];
    float* out = (float*)d_out;
    int rows = in_sizes[0] / ROW_N;   // 2*16*2048 = 65536
    sparsemax_kernel<<<rows, THREADS>>>(in, out);
}